// round 2
// baseline (speedup 1.0000x reference)
#include <cuda_runtime.h>
#include <math.h>

#define N_NODES 50000
#define N_EDGES 800000
#define HEADS   3
#define HID     128
#define HF      (HEADS*HID)   // 384
#define NCLS    6

// ---------------- scratch (device globals; no allocation allowed) ----------------
__device__ float g_h  [(size_t)N_NODES*HF];   // per-layer projected features (N,3,128)
__device__ float g_agg[(size_t)N_NODES*HF];   // aggregation accumulator
__device__ float g_x1 [(size_t)N_NODES*HID];
__device__ float g_x2 [(size_t)N_NODES*HID];
__device__ float g_el [N_NODES*HEADS];
__device__ float g_er [N_NODES*HEADS];
__device__ float g_ew [(size_t)N_EDGES*HEADS];
__device__ float g_mx [N_NODES*HEADS];
__device__ float g_dn [N_NODES*HEADS];

// ---------------- utility ----------------
__device__ __forceinline__ void atomicMaxF(float* addr, float v) {
    // standard signed/unsigned trick; sentinel 0xFFFFFFFF (neg NaN) loses to everything
    if (v >= 0.f) atomicMax((int*)addr, __float_as_int(v));
    else          atomicMin((unsigned int*)addr, __float_as_uint(v));
}

__global__ void k_init() {
    int i = blockIdx.x * blockDim.x + threadIdx.x;
    if (i < N_NODES*HF) g_agg[i] = 0.f;
    if (i < N_NODES*HEADS) {
        g_mx[i] = __uint_as_float(0xFFFFFFFFu); // -NaN sentinel: any real value replaces it
        g_dn[i] = 0.f;
    }
}

// ---------------- SGEMM: C[M,Nc] = A[M,K] @ B[K,Nc] (+bias)(+leaky 0.01) ----------------
// BM=128, BN=64, BK=16, 256 threads, 8x4 per thread
__global__ void sgemm(const float* __restrict__ A, const float* __restrict__ B,
                      const float* __restrict__ bias, float* __restrict__ C,
                      int M, int K, int Nc, int act)
{
    const int BM = 128, BN = 64, BK = 16;
    __shared__ float As[BK][BM + 1];
    __shared__ float Bs[BK][BN];

    int tid = threadIdx.x;
    int m0 = blockIdx.x * BM, n0 = blockIdx.y * BN;
    int tx = tid & 15, ty = tid >> 4;    // ty: row group (8 rows), tx: col group (4 cols)

    float acc[8][4];
    #pragma unroll
    for (int i = 0; i < 8; i++)
        #pragma unroll
        for (int j = 0; j < 4; j++) acc[i][j] = 0.f;

    for (int k0 = 0; k0 < K; k0 += BK) {
        // load A tile: 128x16 = 512 float4, 2 per thread
        #pragma unroll
        for (int i = 0; i < 2; i++) {
            int idx = tid + i * 256;
            int row = idx >> 2;
            int kq  = (idx & 3) * 4;
            float4 v = make_float4(0.f, 0.f, 0.f, 0.f);
            int gr = m0 + row;
            if (gr < M) v = *(const float4*)(A + (size_t)gr * K + k0 + kq);
            As[kq + 0][row] = v.x; As[kq + 1][row] = v.y;
            As[kq + 2][row] = v.z; As[kq + 3][row] = v.w;
        }
        // load B tile: 16x64 = 256 float4, 1 per thread
        {
            int krow = tid >> 4;
            int nq   = (tid & 15) * 4;
            float4 v = *(const float4*)(B + (size_t)(k0 + krow) * Nc + n0 + nq);
            *(float4*)&Bs[krow][nq] = v;
        }
        __syncthreads();
        #pragma unroll
        for (int k = 0; k < BK; k++) {
            float a[8], b[4];
            #pragma unroll
            for (int i = 0; i < 8; i++) a[i] = As[k][ty * 8 + i];
            #pragma unroll
            for (int j = 0; j < 4; j++) b[j] = Bs[k][tx * 4 + j];
            #pragma unroll
            for (int i = 0; i < 8; i++)
                #pragma unroll
                for (int j = 0; j < 4; j++) acc[i][j] += a[i] * b[j];
        }
        __syncthreads();
    }

    #pragma unroll
    for (int i = 0; i < 8; i++) {
        int gr = m0 + ty * 8 + i;
        if (gr >= M) break;
        #pragma unroll
        for (int j = 0; j < 4; j++) {
            int gc = n0 + tx * 4 + j;
            float v = acc[i][j];
            if (bias) v += bias[gc];
            if (act)  v = v > 0.f ? v : 0.01f * v;
            C[(size_t)gr * Nc + gc] = v;
        }
    }
}

// ---------------- attention logits per (node, head): el = <h, al>, er = <h, ar> ----------------
__global__ void k_attn(const float* __restrict__ al, const float* __restrict__ ar)
{
    int w = (blockIdx.x * blockDim.x + threadIdx.x) >> 5;
    int lane = threadIdx.x & 31;
    if (w >= N_NODES * HEADS) return;
    int n = w / HEADS, hh = w - n * HEADS;
    float4 hv = *(const float4*)(g_h + (size_t)n * HF + hh * HID + lane * 4);
    float4 av = *(const float4*)(al + hh * HID + lane * 4);
    float4 bv = *(const float4*)(ar + hh * HID + lane * 4);
    float sl = hv.x * av.x + hv.y * av.y + hv.z * av.z + hv.w * av.w;
    float sr = hv.x * bv.x + hv.y * bv.y + hv.z * bv.z + hv.w * bv.w;
    #pragma unroll
    for (int o = 16; o; o >>= 1) {
        sl += __shfl_xor_sync(0xFFFFFFFFu, sl, o);
        sr += __shfl_xor_sync(0xFFFFFFFFu, sr, o);
    }
    if (lane == 0) { g_el[w] = sl; g_er[w] = sr; }
}

// ---------------- edge pass 1: leaky(el[src]+er[dst], 0.2), segment max ----------------
__global__ void k_edge_max(const int* __restrict__ src, const int* __restrict__ dst)
{
    int e = blockIdx.x * blockDim.x + threadIdx.x;
    if (e >= N_EDGES) return;
    int s = src[e], d = dst[e];
    #pragma unroll
    for (int h = 0; h < HEADS; h++) {
        float v = g_el[s * HEADS + h] + g_er[d * HEADS + h];
        v = v > 0.f ? v : 0.2f * v;
        g_ew[(size_t)e * HEADS + h] = v;
        atomicMaxF(&g_mx[d * HEADS + h], v);
    }
}

// ---------------- edge pass 2: exp(e - m[dst]), segment sum ----------------
__global__ void k_edge_exp(const int* __restrict__ dst)
{
    int e = blockIdx.x * blockDim.x + threadIdx.x;
    if (e >= N_EDGES) return;
    int d = dst[e];
    #pragma unroll
    for (int h = 0; h < HEADS; h++) {
        float x = expf(g_ew[(size_t)e * HEADS + h] - g_mx[d * HEADS + h]);
        g_ew[(size_t)e * HEADS + h] = x;
        atomicAdd(&g_dn[d * HEADS + h], x);
    }
}

// ---------------- edge pass 3: agg[dst] += alpha * h[src], one warp per edge ----------------
__global__ void k_agg(const int* __restrict__ src, const int* __restrict__ dst)
{
    int gw = (blockIdx.x * blockDim.x + threadIdx.x) >> 5;
    int lane = threadIdx.x & 31;
    if (gw >= N_EDGES) return;
    int s = src[gw], d = dst[gw];
    float a = 0.f;
    if (lane < HEADS)
        a = g_ew[(size_t)gw * HEADS + lane] / (g_dn[d * HEADS + lane] + 1e-9f);
    float a0 = __shfl_sync(0xFFFFFFFFu, a, 0);
    float a1 = __shfl_sync(0xFFFFFFFFu, a, 1);
    float a2 = __shfl_sync(0xFFFFFFFFu, a, 2);
    float alph[HEADS] = {a0, a1, a2};
    const float* hs = g_h + (size_t)s * HF;
    float* ad = g_agg + (size_t)d * HF;
    #pragma unroll
    for (int hh = 0; hh < HEADS; hh++) {
        float4 v = *(const float4*)(hs + hh * HID + lane * 4);
        float sc = alph[hh];
        asm volatile("red.global.add.v4.f32 [%0], {%1,%2,%3,%4};"
                     :: "l"(ad + hh * HID + lane * 4),
                        "f"(v.x * sc), "f"(v.y * sc), "f"(v.z * sc), "f"(v.w * sc)
                     : "memory");
    }
}

// ---------------- finalize layer: leaky(agg + b, 0.01), mean over heads ----------------
__global__ void k_final(const float* __restrict__ bias, float* __restrict__ x)
{
    int i = blockIdx.x * blockDim.x + threadIdx.x;
    if (i >= N_NODES * HID) return;
    int n = i >> 7, f = i & 127;
    float sum = 0.f;
    #pragma unroll
    for (int h = 0; h < HEADS; h++) {
        float v = g_agg[(size_t)n * HF + h * HID + f] + bias[h * HID + f];
        v = v > 0.f ? v : 0.01f * v;
        sum += v;
    }
    x[i] = sum * (1.f / 3.f);
}

// ---------------- classifier head: out = x @ lw5 + lb5  (128 -> 6) ----------------
__global__ void k_head(const float* __restrict__ x, const float* __restrict__ w,
                       const float* __restrict__ b, float* __restrict__ out)
{
    int i = blockIdx.x * blockDim.x + threadIdx.x;
    if (i >= N_NODES * NCLS) return;
    int n = i / NCLS, c = i - n * NCLS;
    const float* xr = x + (size_t)n * HID;
    float s = b[c];
    #pragma unroll 8
    for (int k = 0; k < HID; k++) s += xr[k] * w[k * NCLS + c];
    out[i] = s;
}

// ---------------- host ----------------
static void gat_layer(const float* x_in, const float* W, const float* al,
                      const float* ar, const float* b, float* x_out,
                      const int* src, const int* dst, float* p_h)
{
    dim3 gg((N_NODES + 127) / 128, HF / 64);
    sgemm<<<gg, 256>>>(x_in, W, nullptr, p_h, N_NODES, HID, HF, 0);
    k_init<<<(N_NODES * HF + 255) / 256, 256>>>();
    k_attn<<<(N_NODES * HEADS * 32 + 255) / 256, 256>>>(al, ar);
    k_edge_max<<<(N_EDGES + 255) / 256, 256>>>(src, dst);
    k_edge_exp<<<(N_EDGES + 255) / 256, 256>>>(dst);
    k_agg<<<(N_EDGES * 32 + 255) / 256, 256>>>(src, dst);
    k_final<<<(N_NODES * HID + 255) / 256, 256>>>(b, x_out);
}

extern "C" void kernel_launch(void* const* d_in, const int* in_sizes, int n_in,
                              void* d_out, int out_size)
{
    const float* in_feat = (const float*)d_in[0];
    const int*   src     = (const int*)  d_in[1];
    const int*   dst     = (const int*)  d_in[2];
    const float* W1  = (const float*)d_in[3];
    const float* al1 = (const float*)d_in[4];
    const float* ar1 = (const float*)d_in[5];
    const float* b1  = (const float*)d_in[6];
    const float* W2  = (const float*)d_in[7];
    const float* al2 = (const float*)d_in[8];
    const float* ar2 = (const float*)d_in[9];
    const float* b2  = (const float*)d_in[10];
    const float* lw1 = (const float*)d_in[11];
    const float* lb1 = (const float*)d_in[12];
    const float* lw2 = (const float*)d_in[13];
    const float* lb2 = (const float*)d_in[14];
    const float* lw3 = (const float*)d_in[15];
    const float* lb3 = (const float*)d_in[16];
    const float* lw4 = (const float*)d_in[17];
    const float* lb4 = (const float*)d_in[18];
    const float* lw5 = (const float*)d_in[19];
    const float* lb5 = (const float*)d_in[20];

    float *p_h, *p_x1, *p_x2;
    cudaGetSymbolAddress((void**)&p_h,  g_h);
    cudaGetSymbolAddress((void**)&p_x1, g_x1);
    cudaGetSymbolAddress((void**)&p_x2, g_x2);

    // GAT layer 1: in_feat -> g_x1
    gat_layer(in_feat, W1, al1, ar1, b1, p_x1, src, dst, p_h);
    // GAT layer 2: g_x1 -> g_x2
    gat_layer(p_x1, W2, al2, ar2, b2, p_x2, src, dst, p_h);

    // MLP: 4x (128->128, leaky 0.01), ping-pong g_x2 <-> g_x1
    dim3 gm((N_NODES + 127) / 128, HID / 64);
    sgemm<<<gm, 256>>>(p_x2, lw1, lb1, p_x1, N_NODES, HID, HID, 1);
    sgemm<<<gm, 256>>>(p_x1, lw2, lb2, p_x2, N_NODES, HID, HID, 1);
    sgemm<<<gm, 256>>>(p_x2, lw3, lb3, p_x1, N_NODES, HID, HID, 1);
    sgemm<<<gm, 256>>>(p_x1, lw4, lb4, p_x2, N_NODES, HID, HID, 1);

    // head: 128 -> 6
    k_head<<<(N_NODES * NCLS + 255) / 256, 256>>>(p_x2, lw5, lb5, (float*)d_out);
}

// round 3
// speedup vs baseline: 1.6369x; 1.6369x over previous
#include <cuda_runtime.h>
#include <math.h>

#define N_NODES 50000
#define N_EDGES 800000
#define HEADS   3
#define HID     128
#define HF      (HEADS*HID)   // 384
#define NCLS    6

// ---------------- scratch (device globals; no allocation allowed) ----------------
__device__ float g_h  [(size_t)N_NODES*HF];   // projected features (N,3,128)
__device__ float g_x1 [(size_t)N_NODES*HID];
__device__ float g_x2 [(size_t)N_NODES*HID];
__device__ float g_el [N_NODES*HEADS];
__device__ float g_er [N_NODES*HEADS];
__device__ int   g_deg   [N_NODES];
__device__ int   g_rowptr[N_NODES + 1];
__device__ int   g_cursor[N_NODES];
__device__ int   g_csrc  [N_EDGES];           // src node per CSR slot (grouped by dst)

// ---------------- CSR build ----------------
__global__ void k_zero_deg() {
    int i = blockIdx.x * blockDim.x + threadIdx.x;
    if (i < N_NODES) g_deg[i] = 0;
}
__global__ void k_count(const int* __restrict__ dst) {
    int e = blockIdx.x * blockDim.x + threadIdx.x;
    if (e < N_EDGES) atomicAdd(&g_deg[dst[e]], 1);
}
__global__ void k_scan() {   // single block, 1024 threads
    const int T = 1024;
    const int C = (N_NODES + T - 1) / T;
    __shared__ int s[T];
    int t = threadIdx.x;
    int beg = t * C, end = min(beg + C, N_NODES);
    int sum = 0;
    for (int i = beg; i < end; i++) sum += g_deg[i];
    s[t] = sum;
    __syncthreads();
    for (int off = 1; off < T; off <<= 1) {
        int v = (t >= off) ? s[t - off] : 0;
        __syncthreads();
        s[t] += v;
        __syncthreads();
    }
    int run = (t > 0) ? s[t - 1] : 0;
    for (int i = beg; i < end; i++) {
        g_rowptr[i] = run;
        g_cursor[i] = run;
        run += g_deg[i];
    }
    if (t == T - 1) g_rowptr[N_NODES] = run;
}
__global__ void k_scatter(const int* __restrict__ src, const int* __restrict__ dst) {
    int e = blockIdx.x * blockDim.x + threadIdx.x;
    if (e >= N_EDGES) return;
    int pos = atomicAdd(&g_cursor[dst[e]], 1);
    g_csrc[pos] = src[e];
}

// ---------------- SGEMM: C[M,Nc] = A[M,K] @ B[K,Nc] (+bias)(+leaky 0.01) ----------------
// BM=128, BN=128, BK=16, 256 threads, warp-tiled 8x8 per thread
__global__ void sgemm(const float* __restrict__ A, const float* __restrict__ B,
                      const float* __restrict__ bias, float* __restrict__ C,
                      int M, int K, int Nc, int act)
{
    const int BM = 128, BN = 128, BK = 16;
    __shared__ __align__(16) float As[BK][132];   // transposed, padded
    __shared__ __align__(16) float Bs[BK][BN];

    int tid = threadIdx.x;
    int m0 = blockIdx.x * BM, n0 = blockIdx.y * BN;
    int w = tid >> 5, lane = tid & 31;
    int wr = w >> 2, wc = w & 3;        // warps 2x4
    int lr = lane >> 2, lc = lane & 3;  // lanes 8x4
    int row = wr * 64 + lr * 8;
    int col = wc * 32 + lc * 8;

    float acc[8][8];
    #pragma unroll
    for (int i = 0; i < 8; i++)
        #pragma unroll
        for (int j = 0; j < 8; j++) acc[i][j] = 0.f;

    for (int k0 = 0; k0 < K; k0 += BK) {
        // A tile: 128x16 = 512 float4, 2 per thread, stored transposed
        #pragma unroll
        for (int i = 0; i < 2; i++) {
            int j = tid + i * 256;
            int r = j >> 2, kq = (j & 3) << 2;
            float4 v = make_float4(0.f, 0.f, 0.f, 0.f);
            if (m0 + r < M) v = *(const float4*)(A + (size_t)(m0 + r) * K + k0 + kq);
            As[kq + 0][r] = v.x; As[kq + 1][r] = v.y;
            As[kq + 2][r] = v.z; As[kq + 3][r] = v.w;
        }
        // B tile: 16x128 = 512 float4, 2 per thread
        #pragma unroll
        for (int i = 0; i < 2; i++) {
            int j = tid + i * 256;
            int r = j >> 5, c4 = (j & 31) << 2;
            *(float4*)&Bs[r][c4] = *(const float4*)(B + (size_t)(k0 + r) * Nc + n0 + c4);
        }
        __syncthreads();
        #pragma unroll
        for (int k = 0; k < BK; k++) {
            float a[8], b[8];
            *(float4*)(a)     = *(float4*)&As[k][row];
            *(float4*)(a + 4) = *(float4*)&As[k][row + 4];
            *(float4*)(b)     = *(float4*)&Bs[k][col];
            *(float4*)(b + 4) = *(float4*)&Bs[k][col + 4];
            #pragma unroll
            for (int i = 0; i < 8; i++)
                #pragma unroll
                for (int j = 0; j < 8; j++) acc[i][j] += a[i] * b[j];
        }
        __syncthreads();
    }

    float bi[8];
    #pragma unroll
    for (int j = 0; j < 8; j++) bi[j] = bias ? bias[n0 + col + j] : 0.f;

    #pragma unroll
    for (int i = 0; i < 8; i++) {
        int gr = m0 + row + i;
        if (gr >= M) break;
        float out[8];
        #pragma unroll
        for (int j = 0; j < 8; j++) {
            float v = acc[i][j] + bi[j];
            if (act) v = v > 0.f ? v : 0.01f * v;
            out[j] = v;
        }
        *(float4*)(C + (size_t)gr * Nc + n0 + col)     = *(float4*)(out);
        *(float4*)(C + (size_t)gr * Nc + n0 + col + 4) = *(float4*)(out + 4);
    }
}

// ---------------- attention logits per (node, head): el = <h, al>, er = <h, ar> ----------------
__global__ void k_attn(const float* __restrict__ al, const float* __restrict__ ar)
{
    int w = (blockIdx.x * blockDim.x + threadIdx.x) >> 5;
    int lane = threadIdx.x & 31;
    if (w >= N_NODES * HEADS) return;
    int n = w / HEADS, hh = w - n * HEADS;
    float4 hv = *(const float4*)(g_h + (size_t)n * HF + hh * HID + lane * 4);
    float4 av = *(const float4*)(al + hh * HID + lane * 4);
    float4 bv = *(const float4*)(ar + hh * HID + lane * 4);
    float sl = hv.x * av.x + hv.y * av.y + hv.z * av.z + hv.w * av.w;
    float sr = hv.x * bv.x + hv.y * bv.y + hv.z * bv.z + hv.w * bv.w;
    #pragma unroll
    for (int o = 16; o; o >>= 1) {
        sl += __shfl_xor_sync(0xFFFFFFFFu, sl, o);
        sr += __shfl_xor_sync(0xFFFFFFFFu, sr, o);
    }
    if (lane == 0) { g_el[w] = sl; g_er[w] = sr; }
}

// ---------------- fused per-dst softmax + aggregation + bias + leaky + head-mean ----------------
// one warp per dst node
__global__ void k_gather(const float* __restrict__ bias, float* __restrict__ xout)
{
    int gw = (blockIdx.x * blockDim.x + threadIdx.x) >> 5;
    int lane = threadIdx.x & 31;
    if (gw >= N_NODES) return;
    int beg = g_rowptr[gw], end = g_rowptr[gw + 1];

    float er0 = g_er[gw * HEADS + 0];
    float er1 = g_er[gw * HEADS + 1];
    float er2 = g_er[gw * HEADS + 2];

    // pass 1: per-dst max of leaky(el[src]+er[dst]) per head (lane-parallel)
    float m0 = -1e30f, m1 = -1e30f, m2 = -1e30f;
    for (int i = beg + lane; i < end; i += 32) {
        int s = g_csrc[i];
        float e0 = g_el[s * HEADS + 0] + er0; e0 = e0 > 0.f ? e0 : 0.2f * e0;
        float e1 = g_el[s * HEADS + 1] + er1; e1 = e1 > 0.f ? e1 : 0.2f * e1;
        float e2 = g_el[s * HEADS + 2] + er2; e2 = e2 > 0.f ? e2 : 0.2f * e2;
        m0 = fmaxf(m0, e0); m1 = fmaxf(m1, e1); m2 = fmaxf(m2, e2);
    }
    #pragma unroll
    for (int o = 16; o; o >>= 1) {
        m0 = fmaxf(m0, __shfl_xor_sync(0xFFFFFFFFu, m0, o));
        m1 = fmaxf(m1, __shfl_xor_sync(0xFFFFFFFFu, m1, o));
        m2 = fmaxf(m2, __shfl_xor_sync(0xFFFFFFFFu, m2, o));
    }

    // pass 2: exp-weighted gather (all lanes cooperate on feature dim)
    float4 a0 = make_float4(0.f, 0.f, 0.f, 0.f), a1 = a0, a2 = a0;
    float d0 = 0.f, d1 = 0.f, d2 = 0.f;
    for (int i = beg; i < end; i++) {
        int s = g_csrc[i];
        float e0 = g_el[s * HEADS + 0] + er0; e0 = e0 > 0.f ? e0 : 0.2f * e0;
        float e1 = g_el[s * HEADS + 1] + er1; e1 = e1 > 0.f ? e1 : 0.2f * e1;
        float e2 = g_el[s * HEADS + 2] + er2; e2 = e2 > 0.f ? e2 : 0.2f * e2;
        float p0 = __expf(e0 - m0), p1 = __expf(e1 - m1), p2 = __expf(e2 - m2);
        d0 += p0; d1 += p1; d2 += p2;
        const float4* hp = (const float4*)(g_h + (size_t)s * HF);
        float4 h0 = hp[lane];
        float4 h1 = hp[32 + lane];
        float4 h2 = hp[64 + lane];
        a0.x += p0 * h0.x; a0.y += p0 * h0.y; a0.z += p0 * h0.z; a0.w += p0 * h0.w;
        a1.x += p1 * h1.x; a1.y += p1 * h1.y; a1.z += p1 * h1.z; a1.w += p1 * h1.w;
        a2.x += p2 * h2.x; a2.y += p2 * h2.y; a2.z += p2 * h2.z; a2.w += p2 * h2.w;
    }
    float i0 = 1.f / (d0 + 1e-9f);
    float i1 = 1.f / (d1 + 1e-9f);
    float i2 = 1.f / (d2 + 1e-9f);

    float4 b0 = *(const float4*)(bias + 0 * HID + lane * 4);
    float4 b1 = *(const float4*)(bias + 1 * HID + lane * 4);
    float4 b2 = *(const float4*)(bias + 2 * HID + lane * 4);

    float4 o;
    float v;
    v = a0.x * i0 + b0.x; v = v > 0.f ? v : 0.01f * v; o.x  = v;
    v = a1.x * i1 + b1.x; v = v > 0.f ? v : 0.01f * v; o.x += v;
    v = a2.x * i2 + b2.x; v = v > 0.f ? v : 0.01f * v; o.x += v;
    v = a0.y * i0 + b0.y; v = v > 0.f ? v : 0.01f * v; o.y  = v;
    v = a1.y * i1 + b1.y; v = v > 0.f ? v : 0.01f * v; o.y += v;
    v = a2.y * i2 + b2.y; v = v > 0.f ? v : 0.01f * v; o.y += v;
    v = a0.z * i0 + b0.z; v = v > 0.f ? v : 0.01f * v; o.z  = v;
    v = a1.z * i1 + b1.z; v = v > 0.f ? v : 0.01f * v; o.z += v;
    v = a2.z * i2 + b2.z; v = v > 0.f ? v : 0.01f * v; o.z += v;
    v = a0.w * i0 + b0.w; v = v > 0.f ? v : 0.01f * v; o.w  = v;
    v = a1.w * i1 + b1.w; v = v > 0.f ? v : 0.01f * v; o.w += v;
    v = a2.w * i2 + b2.w; v = v > 0.f ? v : 0.01f * v; o.w += v;
    const float third = 1.f / 3.f;
    o.x *= third; o.y *= third; o.z *= third; o.w *= third;
    *(float4*)(xout + (size_t)gw * HID + lane * 4) = o;
}

// ---------------- classifier head: out = x @ lw5 + lb5  (128 -> 6) ----------------
__global__ void k_head(const float* __restrict__ x, const float* __restrict__ w,
                       const float* __restrict__ b, float* __restrict__ out)
{
    int i = blockIdx.x * blockDim.x + threadIdx.x;
    if (i >= N_NODES * NCLS) return;
    int n = i / NCLS, c = i - n * NCLS;
    const float* xr = x + (size_t)n * HID;
    float s = b[c];
    #pragma unroll 8
    for (int k = 0; k < HID; k++) s += xr[k] * w[k * NCLS + c];
    out[i] = s;
}

// ---------------- host ----------------
static void gat_layer(const float* x_in, const float* W, const float* al,
                      const float* ar, const float* b, float* x_out, float* p_h)
{
    dim3 gg((N_NODES + 127) / 128, HF / 128);
    sgemm<<<gg, 256>>>(x_in, W, nullptr, p_h, N_NODES, HID, HF, 0);
    k_attn<<<(N_NODES * HEADS * 32 + 255) / 256, 256>>>(al, ar);
    k_gather<<<(N_NODES * 32 + 255) / 256, 256>>>(b, x_out);
}

extern "C" void kernel_launch(void* const* d_in, const int* in_sizes, int n_in,
                              void* d_out, int out_size)
{
    const float* in_feat = (const float*)d_in[0];
    const int*   src     = (const int*)  d_in[1];
    const int*   dst     = (const int*)  d_in[2];
    const float* W1  = (const float*)d_in[3];
    const float* al1 = (const float*)d_in[4];
    const float* ar1 = (const float*)d_in[5];
    const float* b1  = (const float*)d_in[6];
    const float* W2  = (const float*)d_in[7];
    const float* al2 = (const float*)d_in[8];
    const float* ar2 = (const float*)d_in[9];
    const float* b2  = (const float*)d_in[10];
    const float* lw1 = (const float*)d_in[11];
    const float* lb1 = (const float*)d_in[12];
    const float* lw2 = (const float*)d_in[13];
    const float* lb2 = (const float*)d_in[14];
    const float* lw3 = (const float*)d_in[15];
    const float* lb3 = (const float*)d_in[16];
    const float* lw4 = (const float*)d_in[17];
    const float* lb4 = (const float*)d_in[18];
    const float* lw5 = (const float*)d_in[19];
    const float* lb5 = (const float*)d_in[20];

    float *p_h, *p_x1, *p_x2;
    cudaGetSymbolAddress((void**)&p_h,  g_h);
    cudaGetSymbolAddress((void**)&p_x1, g_x1);
    cudaGetSymbolAddress((void**)&p_x2, g_x2);

    // build CSR once (same graph both layers)
    k_zero_deg<<<(N_NODES + 255) / 256, 256>>>();
    k_count<<<(N_EDGES + 255) / 256, 256>>>(dst);
    k_scan<<<1, 1024>>>();
    k_scatter<<<(N_EDGES + 255) / 256, 256>>>(src, dst);

    // GAT layer 1: in_feat -> g_x1
    gat_layer(in_feat, W1, al1, ar1, b1, p_x1, p_h);
    // GAT layer 2: g_x1 -> g_x2
    gat_layer(p_x1, W2, al2, ar2, b2, p_x2, p_h);

    // MLP: 4x (128->128, leaky 0.01), ping-pong g_x2 <-> g_x1
    dim3 gm((N_NODES + 127) / 128, 1);
    sgemm<<<gm, 256>>>(p_x2, lw1, lb1, p_x1, N_NODES, HID, HID, 1);
    sgemm<<<gm, 256>>>(p_x1, lw2, lb2, p_x2, N_NODES, HID, HID, 1);
    sgemm<<<gm, 256>>>(p_x2, lw3, lb3, p_x1, N_NODES, HID, HID, 1);
    sgemm<<<gm, 256>>>(p_x1, lw4, lb4, p_x2, N_NODES, HID, HID, 1);

    // head: 128 -> 6
    k_head<<<(N_NODES * NCLS + 255) / 256, 256>>>(p_x2, lw5, lb5, (float*)d_out);
}